// round 16
// baseline (speedup 1.0000x reference)
#include <cuda_runtime.h>
#include <math.h>

// Problem dims (fixed by the dataset)
#define NB 4
#define CC 256
#define TT 16
#define HH 56
#define WW 56
#define KK 16
#define TP 8
#define HP 28
#define WP 28
#define PLANE (TT*HH*WW)        // 50176, channel stride in vw
#define OPLANE (TP*HP*WP)       // 6272, channel stride in out
#define SPLANE (HH*WW)          // 3136 spatial points per (n,t)

// Scratch: exp map [N,T,H,W] and pre-built tf32 B-fragments.
__device__ float g_emap[NB * TT * HH * WW];
__device__ uint4 g_bfrag[NB * 2048];   // [n][step s][n-half h][lane]

__device__ __forceinline__ unsigned long long fma2(unsigned long long a,
                                                   unsigned long long b,
                                                   unsigned long long c) {
    unsigned long long d;
    asm("fma.rn.f32x2 %0, %1, %2, %3;" : "=l"(d) : "l"(a), "l"(b), "l"(c));
    return d;
}

__device__ __forceinline__ float lo32(unsigned long long v) {
    return __uint_as_float((unsigned)v);
}
__device__ __forceinline__ float hi32(unsigned long long v) {
    return __uint_as_float((unsigned)(v >> 32));
}

__device__ __forceinline__ unsigned tf32_rna(float x) {
    unsigned r;
    asm("cvt.rna.tf32.f32 %0, %1;" : "=r"(r) : "f"(x));
    return r;
}

// D(16x8) += A(16x8) * B(8x8), tf32 inputs, f32 accum.
__device__ __forceinline__ void mma8(float* d, const unsigned* a,
                                     unsigned b0, unsigned b1) {
    asm("mma.sync.aligned.m16n8k8.row.col.f32.tf32.tf32.f32 "
        "{%0,%1,%2,%3}, {%4,%5,%6,%7}, {%8,%9}, {%0,%1,%2,%3};"
        : "+f"(d[0]), "+f"(d[1]), "+f"(d[2]), "+f"(d[3])
        : "r"(a[0]), "r"(a[1]), "r"(a[2]), "r"(a[3]), "r"(b0), "r"(b1));
}

// ---------------------------------------------------------------------------
// Kernel 0: build tf32 hi/lo B-fragments for all n (one-shot, tiny).
// ---------------------------------------------------------------------------
__global__ void bprep_kernel(const float* __restrict__ wmat) {
    const int j = blockIdx.x * 256 + threadIdx.x;
    if (j >= NB * 2048) return;
    const int n = j >> 11;
    const int r = j & 2047;
    const int s = r >> 6;
    const int h = (r >> 5) & 1;
    const int l = r & 31;
    const int tg = l & 3, gg = l >> 2;
    const int kw = 8 * h + gg;        // word index (n of GEMM)
    const int c  = 8 * s + tg;        // channel (k of GEMM)
    const float* wn = wmat + (size_t)n * KK * CC;
    float b0 = wn[kw * CC + c];
    float b1 = wn[kw * CC + c + 4];
    unsigned b0h = tf32_rna(b0), b1h = tf32_rna(b1);
    unsigned b0l = tf32_rna(b0 - __uint_as_float(b0h));
    unsigned b1l = tf32_rna(b1 - __uint_as_float(b1h));
    g_bfrag[j] = make_uint4(b0h, b1h, b0l, b1l);
}

// ---------------------------------------------------------------------------
// Kernel 1: emap via mma.sync tf32 (hi/lo split, fp32-quality), HALF-BATCH:
// covers n = 2*half + blockIdx.z. Each warp does ONE 32-position m-pass so
// a half-launch still fills the chip: grid (14,16,2) x 7 warps = 3136 warps
// = 21 warps/SM (same residency as the R14 full launch). B-fragments read
// from the global table (L2-hot). Per c-step: 8 LDG.32 + 2 LDG.128(bfrag)
// + 12 MMA.
// ---------------------------------------------------------------------------
__global__ __launch_bounds__(224, 4) void emap_kernel(const float* __restrict__ vw,
                                                      int half) {
    const int n  = half * 2 + blockIdx.z;
    const int tt = blockIdx.y;
    const int lane = threadIdx.x;
    const int t = lane & 3;           // threadID in group (col of A, row of B)
    const int g = lane >> 2;          // group (row of A, col of B)
    const int wg = blockIdx.x * 7 + threadIdx.y;   // 0..97
    const int m0 = wg * 32;

    const size_t base_nt = (size_t)n * CC * PLANE + (size_t)tt * SPLANE;
    const float* pa = vw + base_nt + (size_t)t * PLANE + m0 + g;
    const uint4* bf = g_bfrag + n * 2048;

    float D[2][2][4];   // [tile][n-half][frag]
#pragma unroll
    for (int i = 0; i < 2; i++)
#pragma unroll
        for (int h = 0; h < 2; h++)
#pragma unroll
            for (int e = 0; e < 4; e++) D[i][h][e] = 0.f;

    for (int s = 0; s < 32; s++) {
        // A fragments (raw f32): a0=(g,t) a1=(g+8,t) a2=(g,t+4) a3=(g+8,t+4)
        float araw[2][4];
        araw[0][0] = pa[0];
        araw[0][1] = pa[8];
        araw[0][2] = pa[4 * PLANE];
        araw[0][3] = pa[4 * PLANE + 8];
        araw[1][0] = pa[16];
        araw[1][1] = pa[24];
        araw[1][2] = pa[4 * PLANE + 16];
        araw[1][3] = pa[4 * PLANE + 24];
        pa += 8 * (size_t)PLANE;

        uint4 B0 = __ldg(bf + s * 64 + lane);        // n-half 0 (words 0-7)
        uint4 B1 = __ldg(bf + s * 64 + 32 + lane);   // n-half 1 (words 8-15)

        unsigned ah[2][4], al[2][4];
#pragma unroll
        for (int i = 0; i < 2; i++)
#pragma unroll
            for (int e = 0; e < 4; e++) {
                ah[i][e] = tf32_rna(araw[i][e]);
                al[i][e] = tf32_rna(araw[i][e] - __uint_as_float(ah[i][e]));
            }

#pragma unroll
        for (int i = 0; i < 2; i++) {
            mma8(D[i][0], ah[i], B0.x, B0.y);   // ah*bh
            mma8(D[i][0], al[i], B0.x, B0.y);   // al*bh
            mma8(D[i][0], ah[i], B0.z, B0.w);   // ah*bl
            mma8(D[i][1], ah[i], B1.x, B1.y);
            mma8(D[i][1], al[i], B1.x, B1.y);
            mma8(D[i][1], ah[i], B1.z, B1.w);
        }
    }

    const size_t eb = ((size_t)n * TT + tt) * SPLANE;
#pragma unroll
    for (int i = 0; i < 2; i++) {
        float mlo = fmaxf(fmaxf(D[i][0][0], D[i][0][1]),
                          fmaxf(D[i][1][0], D[i][1][1]));   // row g
        float mhi = fmaxf(fmaxf(D[i][0][2], D[i][0][3]),
                          fmaxf(D[i][1][2], D[i][1][3]));   // row g+8
        mlo = fmaxf(mlo, __shfl_xor_sync(0xffffffffu, mlo, 1));
        mlo = fmaxf(mlo, __shfl_xor_sync(0xffffffffu, mlo, 2));
        mhi = fmaxf(mhi, __shfl_xor_sync(0xffffffffu, mhi, 1));
        mhi = fmaxf(mhi, __shfl_xor_sync(0xffffffffu, mhi, 2));
        if (t == 0) {
            // sqrt(C) = 16 exactly
            g_emap[eb + m0 + 16 * i + g]     = expf(mlo * 0.0625f);
            g_emap[eb + m0 + 16 * i + g + 8] = expf(mhi * 0.0625f);
        }
    }
}

// ---------------------------------------------------------------------------
// Kernel 2 (R8 pool body), HALF-BATCH: z = n_local*2 + chalf, n = 2*half +
// n_local. Runs immediately after emap(half), so its vw reads hit L2
// (103MB slab < 126MB L2). grid (HP, TP, 4), block (32,8).
// ---------------------------------------------------------------------------
__global__ __launch_bounds__(256, 4) void pool_kernel(const float* __restrict__ vw,
                                                      float* __restrict__ out,
                                                      int half) {
    const int n     = half * 2 + (blockIdx.z >> 1);
    const int chalf = blockIdx.z & 1;
    const int tp = blockIdx.y;
    const int hp = blockIdx.x;
    const int tid = threadIdx.y * 32 + threadIdx.x;

    __shared__ float4 wpk[9 * 14];
    __shared__ float  wem[9 * 14];
    __shared__ float  wrd[14 * 2];

    if (tid < 126) {
        const int r  = tid / 14;
        const int w2 = tid - r * 14;
        const int dt = r / 3, dh = r - dt * 3;
        const int t = 2 * tp - 1 + dt;
        const int h = 2 * hp - 1 + dh;
        const bool rv = (t >= 0) && (h >= 0);
        const int tc = t > 0 ? t : 0;
        const int hc = h > 0 ? h : 0;
        const float* ep = g_emap + ((size_t)n * TT + tc) * SPLANE + (size_t)hc * WW;
        const int wb = 4 * w2;
        float em1 = (rv && wb > 0) ? ep[wb - 1] : 0.f;
        float e0 = rv ? ep[wb + 0] : 0.f;
        float e1 = rv ? ep[wb + 1] : 0.f;
        float e2 = rv ? ep[wb + 2] : 0.f;
        float e3 = rv ? ep[wb + 3] : 0.f;
        wpk[tid] = make_float4(e0, e1, e2, e3);
        wem[tid] = em1;
    }
    __syncthreads();
    if (tid < 28) {
        const int w2i = tid % 14;
        const int sel = tid / 14;
        float s = 0.f;
#pragma unroll
        for (int r = 0; r < 9; r++) {
            float4 f = wpk[r * 14 + w2i];
            s += sel ? (f.y + f.z + f.w) : (wem[r * 14 + w2i] + f.x + f.y);
        }
        wrd[w2i * 2 + sel] = 1.0f / s;
    }
    __syncthreads();

    const int lane = threadIdx.x;
    const int w2   = (lane & 15) < 14 ? (lane & 15) : 13;
    const int csel = lane >> 4;
    const bool act = (lane & 15) < 14;

    const float rden0 = wrd[w2 * 2 + 0];
    const float rden1 = wrd[w2 * 2 + 1];

    int rowoff[9];
#pragma unroll
    for (int r = 0; r < 9; r++) {
        const int dt = r / 3, dh = r - dt * 3;
        const int t = 2 * tp - 1 + dt;
        const int h = 2 * hp - 1 + dh;
        const int tc = t > 0 ? t : 0;
        const int hc = h > 0 ? h : 0;
        rowoff[r] = (tc * HH + hc) * WW;
    }

    const float* basep = vw + (size_t)n * CC * PLANE + 4 * w2;
    float* outbase = out + (((size_t)n * CC * TP + tp) * HP + hp) * WP + 2 * w2;

    const int cbeg = chalf * (CC / 2);
    const ulonglong2* wpk2 = (const ulonglong2*)wpk;

    for (int c0 = cbeg + threadIdx.y * 4; c0 < cbeg + CC / 2; c0 += 32) {
        const int cA = c0 + 2 * csel;
        const float* pA = basep + (size_t)cA * PLANE;
        const float* pB = pA + PLANE;
        unsigned long long a0A = 0ull, a1A = 0ull, a0B = 0ull, a1B = 0ull;
        float sxA = 0.f, spA = 0.f, sxB = 0.f, spB = 0.f;
#pragma unroll
        for (int r = 0; r < 9; r++) {
            ulonglong2 xA = __ldg((const ulonglong2*)(pA + rowoff[r]));
            ulonglong2 xB = __ldg((const ulonglong2*)(pB + rowoff[r]));
            ulonglong2 wpr = wpk2[r * 14 + w2];
            a0A = fma2(wpr.x, xA.x, a0A);
            a1A = fma2(wpr.y, xA.y, a1A);
            a0B = fma2(wpr.x, xB.x, a0B);
            a1B = fma2(wpr.y, xB.y, a1B);
            sxA = fmaf(hi32(wpr.x), hi32(xA.x), sxA);
            spA = fmaf(hi32(wpr.y), hi32(xA.y), spA);
            sxB = fmaf(hi32(wpr.x), hi32(xB.x), sxB);
            spB = fmaf(hi32(wpr.y), hi32(xB.y), spB);
        }
        float spAm = __shfl_up_sync(0xffffffffu, spA, 1);
        float spBm = __shfl_up_sync(0xffffffffu, spB, 1);
        if ((lane & 15) == 0) { spAm = 0.f; spBm = 0.f; }
        if (act) {
            float2 oA = make_float2((lo32(a0A) + hi32(a0A) + spAm) * rden0,
                                    (lo32(a1A) + hi32(a1A) + sxA) * rden1);
            float2 oB = make_float2((lo32(a0B) + hi32(a0B) + spBm) * rden0,
                                    (lo32(a1B) + hi32(a1B) + sxB) * rden1);
            *(float2*)(outbase + (size_t)cA * OPLANE) = oA;
            *(float2*)(outbase + (size_t)(cA + 1) * OPLANE) = oB;
        }
    }
}

// ---------------------------------------------------------------------------
// Serial half-batch phasing on ONE stream (no streams/events — the R15
// multi-stream attempt both leaked and serialized). L2 reuse comes from
// ordering: pool(half) runs right after emap(half) while the 103MB vw slab
// is still L2-resident.
// ---------------------------------------------------------------------------
extern "C" void kernel_launch(void* const* d_in, const int* in_sizes, int n_in,
                              void* d_out, int out_size) {
    const float* a0 = (const float*)d_in[0];
    const float* a1 = (const float*)d_in[1];
    const float* vw   = (in_sizes[0] > in_sizes[1]) ? a0 : a1;
    const float* wmat = (in_sizes[0] > in_sizes[1]) ? a1 : a0;
    float* out = (float*)d_out;

    bprep_kernel<<<32, 256>>>(wmat);
    for (int half = 0; half < 2; half++) {
        emap_kernel<<<dim3(14, TT, 2), dim3(32, 7)>>>(vw, half);
        pool_kernel<<<dim3(HP, TP, 4), dim3(32, 8)>>>(vw, out, half);
    }
}

// round 17
// speedup vs baseline: 1.1906x; 1.1906x over previous
#include <cuda_runtime.h>
#include <math.h>

// Problem dims (fixed by the dataset)
#define NB 4
#define CC 256
#define TT 16
#define HH 56
#define WW 56
#define KK 16
#define TP 8
#define HP 28
#define WP 28
#define PLANE (TT*HH*WW)        // 50176, channel stride in vw
#define OPLANE (TP*HP*WP)       // 6272, channel stride in out
#define SPLANE (HH*WW)          // 3136 spatial points per (n,t)

// Scratch: exp map, [N, T, H, W]
__device__ float g_emap[NB * TT * HH * WW];

__device__ __forceinline__ unsigned long long fma2(unsigned long long a,
                                                   unsigned long long b,
                                                   unsigned long long c) {
    unsigned long long d;
    asm("fma.rn.f32x2 %0, %1, %2, %3;" : "=l"(d) : "l"(a), "l"(b), "l"(c));
    return d;
}

__device__ __forceinline__ float lo32(unsigned long long v) {
    return __uint_as_float((unsigned)v);
}
__device__ __forceinline__ float hi32(unsigned long long v) {
    return __uint_as_float((unsigned)(v >> 32));
}

__device__ __forceinline__ unsigned tf32_rna(float x) {
    unsigned r;
    asm("cvt.rna.tf32.f32 %0, %1;" : "=r"(r) : "f"(x));
    return r;
}

// D(16x8) += A(16x8) * B(8x8), tf32 inputs, f32 accum.
__device__ __forceinline__ void mma8(float* d, const unsigned* a,
                                     unsigned b0, unsigned b1) {
    asm("mma.sync.aligned.m16n8k8.row.col.f32.tf32.tf32.f32 "
        "{%0,%1,%2,%3}, {%4,%5,%6,%7}, {%8,%9}, {%0,%1,%2,%3};"
        : "+f"(d[0]), "+f"(d[1]), "+f"(d[2]), "+f"(d[3])
        : "r"(a[0]), "r"(a[1]), "r"(a[2]), "r"(a[3]), "r"(b0), "r"(b1));
}

// ---------------------------------------------------------------------------
// Kernel 1 (R14 structure — best measured emap — minus the A-low term):
// emap GEMM D[m,k] = vw^T[m,c] w^T[c,k] on mma.sync m16n8k8 tf32.
// Precision: B split hi+lo (staged once per block), A used in tf32-hi only:
// D = ah*bh + ah*bl. A-truncation error ~1e-4 rel, well under the 1e-3 gate,
// and it deletes 16 ALU instr + 4 MMAs per step per thread (issue -43%).
// Per warp: 64 positions (2 passes x 2 m16 tiles); per c-step: 8 LDG.32 +
// 2 LDS.128 + 8 cvt + 8 MMA. block (32,7), grid (7,16,4), (224,4).
// ---------------------------------------------------------------------------
__global__ __launch_bounds__(224, 4) void emap_kernel(const float* __restrict__ vw,
                                                      const float* __restrict__ wmat) {
    // [step s][n-half h][lane] = {b0h, b1h, b0l, b1l}; b0 = B[k=8s+t][n=8h+g]
    __shared__ uint4 bfrag[32 * 2 * 32];   // 32 KB

    const int n  = blockIdx.z;
    const int tt = blockIdx.y;
    const int tid = threadIdx.y * 32 + threadIdx.x;

    // Stage w (layout [k_word][c]) into fragment order with hi/lo tf32 split.
    const float* wn = wmat + (size_t)n * KK * CC;
    for (int j = tid; j < 2048; j += 224) {
        const int s = j >> 6;
        const int h = (j >> 5) & 1;
        const int l = j & 31;
        const int tg = l & 3, gg = l >> 2;
        const int kw = 8 * h + gg;        // word index (n of GEMM)
        const int c  = 8 * s + tg;        // channel (k of GEMM)
        float b0 = wn[kw * CC + c];
        float b1 = wn[kw * CC + c + 4];
        unsigned b0h = tf32_rna(b0), b1h = tf32_rna(b1);
        unsigned b0l = tf32_rna(b0 - __uint_as_float(b0h));
        unsigned b1l = tf32_rna(b1 - __uint_as_float(b1h));
        bfrag[j] = make_uint4(b0h, b1h, b0l, b1l);
    }
    __syncthreads();

    const int lane = threadIdx.x;
    const int t = lane & 3;           // threadID in group (col of A, row of B)
    const int g = lane >> 2;          // group (row of A, col of B)
    const int mwarp = (blockIdx.x * 7 + threadIdx.y) * 64;  // warp's 64 positions
    const size_t base_nt = (size_t)n * CC * PLANE + (size_t)tt * SPLANE;
    const size_t eb = ((size_t)n * TT + tt) * SPLANE;

#pragma unroll
    for (int pass = 0; pass < 2; pass++) {
        const int m0 = mwarp + 32 * pass;
        const float* pa = vw + base_nt + (size_t)t * PLANE + m0 + g;

        float D[2][2][4];   // [tile][n-half][frag]
#pragma unroll
        for (int i = 0; i < 2; i++)
#pragma unroll
            for (int h = 0; h < 2; h++)
#pragma unroll
                for (int e = 0; e < 4; e++) D[i][h][e] = 0.f;

        for (int s = 0; s < 32; s++) {
            // A fragments (raw f32): a0=(g,t) a1=(g+8,t) a2=(g,t+4) a3=(g+8,t+4)
            float araw[2][4];
            araw[0][0] = pa[0];
            araw[0][1] = pa[8];
            araw[0][2] = pa[4 * PLANE];
            araw[0][3] = pa[4 * PLANE + 8];
            araw[1][0] = pa[16];
            araw[1][1] = pa[24];
            araw[1][2] = pa[4 * PLANE + 16];
            araw[1][3] = pa[4 * PLANE + 24];
            pa += 8 * (size_t)PLANE;

            unsigned ah[2][4];
#pragma unroll
            for (int i = 0; i < 2; i++)
#pragma unroll
                for (int e = 0; e < 4; e++)
                    ah[i][e] = tf32_rna(araw[i][e]);

            uint4 B0 = bfrag[s * 64 + lane];        // n-half 0 (words 0-7)
            uint4 B1 = bfrag[s * 64 + 32 + lane];   // n-half 1 (words 8-15)

#pragma unroll
            for (int i = 0; i < 2; i++) {
                mma8(D[i][0], ah[i], B0.x, B0.y);   // ah*bh
                mma8(D[i][0], ah[i], B0.z, B0.w);   // ah*bl
                mma8(D[i][1], ah[i], B1.x, B1.y);
                mma8(D[i][1], ah[i], B1.z, B1.w);
            }
        }

        // Max over the 16 words, exp, store.
#pragma unroll
        for (int i = 0; i < 2; i++) {
            float mlo = fmaxf(fmaxf(D[i][0][0], D[i][0][1]),
                              fmaxf(D[i][1][0], D[i][1][1]));   // row g
            float mhi = fmaxf(fmaxf(D[i][0][2], D[i][0][3]),
                              fmaxf(D[i][1][2], D[i][1][3]));   // row g+8
            mlo = fmaxf(mlo, __shfl_xor_sync(0xffffffffu, mlo, 1));
            mlo = fmaxf(mlo, __shfl_xor_sync(0xffffffffu, mlo, 2));
            mhi = fmaxf(mhi, __shfl_xor_sync(0xffffffffu, mhi, 1));
            mhi = fmaxf(mhi, __shfl_xor_sync(0xffffffffu, mhi, 2));
            if (t == 0) {
                // sqrt(C) = 16 exactly
                g_emap[eb + m0 + 16 * i + g]     = expf(mlo * 0.0625f);
                g_emap[eb + m0 + 16 * i + g + 8] = expf(mhi * 0.0625f);
            }
        }
    }
}

// ---------------------------------------------------------------------------
// Kernel 2 (R8 structure — best measured pool, near DRAM roofline): lane owns
// output pair (2w2, 2w2+1); one LDG.128 per row per channel; the w-1 corner
// term comes from the left lane via one shfl_up per channel after the r-loop.
// grid (HP, TP, NB*2), block (32,8).
// ---------------------------------------------------------------------------
__global__ __launch_bounds__(256, 4) void pool_kernel(const float* __restrict__ vw,
                                                      float* __restrict__ out) {
    const int n     = blockIdx.z >> 1;
    const int chalf = blockIdx.z & 1;
    const int tp = blockIdx.y;
    const int hp = blockIdx.x;
    const int tid = threadIdx.y * 32 + threadIdx.x;

    __shared__ float4 wpk[9 * 14];   // {e[4w2], e[4w2+1], e[4w2+2], e[4w2+3]} per (r,w2)
    __shared__ float  wem[9 * 14];   // e[4w2-1]  (denominator only)
    __shared__ float  wrd[14 * 2];   // 1/denominator for outputs (2w2, 2w2+1)

    // Fill window-weight tables (126 items).
    if (tid < 126) {
        const int r  = tid / 14;
        const int w2 = tid - r * 14;
        const int dt = r / 3, dh = r - dt * 3;
        const int t = 2 * tp - 1 + dt;
        const int h = 2 * hp - 1 + dh;
        const bool rv = (t >= 0) && (h >= 0);
        const int tc = t > 0 ? t : 0;
        const int hc = h > 0 ? h : 0;
        const float* ep = g_emap + ((size_t)n * TT + tc) * SPLANE + (size_t)hc * WW;
        const int wb = 4 * w2;
        float em1 = (rv && wb > 0) ? ep[wb - 1] : 0.f;
        float e0 = rv ? ep[wb + 0] : 0.f;
        float e1 = rv ? ep[wb + 1] : 0.f;
        float e2 = rv ? ep[wb + 2] : 0.f;
        float e3 = rv ? ep[wb + 3] : 0.f;
        wpk[tid] = make_float4(e0, e1, e2, e3);
        wem[tid] = em1;
    }
    __syncthreads();
    if (tid < 28) {
        const int w2i = tid % 14;
        const int sel = tid / 14;
        float s = 0.f;
#pragma unroll
        for (int r = 0; r < 9; r++) {
            float4 f = wpk[r * 14 + w2i];
            s += sel ? (f.y + f.z + f.w) : (wem[r * 14 + w2i] + f.x + f.y);
        }
        wrd[w2i * 2 + sel] = 1.0f / s;
    }
    __syncthreads();

    const int lane = threadIdx.x;
    const int w2   = (lane & 15) < 14 ? (lane & 15) : 13;  // clamp
    const int csel = lane >> 4;                            // channel select 0/1
    const bool act = (lane & 15) < 14;

    const float rden0 = wrd[w2 * 2 + 0];
    const float rden1 = wrd[w2 * 2 + 1];

    int rowoff[9];
#pragma unroll
    for (int r = 0; r < 9; r++) {
        const int dt = r / 3, dh = r - dt * 3;
        const int t = 2 * tp - 1 + dt;
        const int h = 2 * hp - 1 + dh;
        const int tc = t > 0 ? t : 0;
        const int hc = h > 0 ? h : 0;
        rowoff[r] = (tc * HH + hc) * WW;
    }

    const float* basep = vw + (size_t)n * CC * PLANE + 4 * w2;
    float* outbase = out + (((size_t)n * CC * TP + tp) * HP + hp) * WP + 2 * w2;

    const int cbeg = chalf * (CC / 2);
    const ulonglong2* wpk2 = (const ulonglong2*)wpk;

    // 4 channels per warp-iteration: this lane handles cA=c0+2*csel, cB=cA+1.
    for (int c0 = cbeg + threadIdx.y * 4; c0 < cbeg + CC / 2; c0 += 32) {
        const int cA = c0 + 2 * csel;
        const float* pA = basep + (size_t)cA * PLANE;
        const float* pB = pA + PLANE;
        unsigned long long a0A = 0ull, a1A = 0ull, a0B = 0ull, a1B = 0ull;
        float sxA = 0.f, spA = 0.f, sxB = 0.f, spB = 0.f;
#pragma unroll
        for (int r = 0; r < 9; r++) {
            ulonglong2 xA = __ldg((const ulonglong2*)(pA + rowoff[r]));
            ulonglong2 xB = __ldg((const ulonglong2*)(pB + rowoff[r]));
            ulonglong2 wpr = wpk2[r * 14 + w2];   // .x = (e0,e1), .y = (e2,e3)
            a0A = fma2(wpr.x, xA.x, a0A);
            a1A = fma2(wpr.y, xA.y, a1A);
            a0B = fma2(wpr.x, xB.x, a0B);
            a1B = fma2(wpr.y, xB.y, a1B);
            sxA = fmaf(hi32(wpr.x), hi32(xA.x), sxA);   // e1*v1 -> own out1
            spA = fmaf(hi32(wpr.y), hi32(xA.y), spA);   // e3*v3 -> right nbr out0
            sxB = fmaf(hi32(wpr.x), hi32(xB.x), sxB);
            spB = fmaf(hi32(wpr.y), hi32(xB.y), spB);
        }
        float spAm = __shfl_up_sync(0xffffffffu, spA, 1);
        float spBm = __shfl_up_sync(0xffffffffu, spB, 1);
        if ((lane & 15) == 0) { spAm = 0.f; spBm = 0.f; }
        if (act) {
            float2 oA = make_float2((lo32(a0A) + hi32(a0A) + spAm) * rden0,
                                    (lo32(a1A) + hi32(a1A) + sxA) * rden1);
            float2 oB = make_float2((lo32(a0B) + hi32(a0B) + spBm) * rden0,
                                    (lo32(a1B) + hi32(a1B) + sxB) * rden1);
            *(float2*)(outbase + (size_t)cA * OPLANE) = oA;
            *(float2*)(outbase + (size_t)(cA + 1) * OPLANE) = oB;
        }
    }
}

extern "C" void kernel_launch(void* const* d_in, const int* in_sizes, int n_in,
                              void* d_out, int out_size) {
    const float* a0 = (const float*)d_in[0];
    const float* a1 = (const float*)d_in[1];
    // vw is the big tensor (51,380,224 elems); w is 16,384 elems.
    const float* vw   = (in_sizes[0] > in_sizes[1]) ? a0 : a1;
    const float* wmat = (in_sizes[0] > in_sizes[1]) ? a1 : a0;
    float* out = (float*)d_out;

    emap_kernel<<<dim3(7, TT, NB), dim3(32, 7)>>>(vw, wmat);
    pool_kernel<<<dim3(HP, TP, NB * 2), dim3(32, 8)>>>(vw, out);
}